// round 17
// baseline (speedup 1.0000x reference)
#include <cuda_runtime.h>
#include <cuda_bf16.h>

// R14 = R13 with VECTORIZED constant access. sm_103a has no cbank-as-operand:
// every cC[] use is an explicit LDC/LDCU (GPR-dest LDC floor = 8 cyc/SMSP),
// and regs=69 shows coefficients are re-read per iteration -> the constant
// port is plausibly the real binder (~520 cyc/warp-iter). Repack as
// float4 cC4[18]: 17 LDC.128 per iteration instead of ~65 scalar LDCs.
// Everything else (PDL, permutation setup, per-row eval, double-buffer,
// guard specialization) is identical to the committed R13.
// Linear layout: [0:5) c1, [5:20) c2 lex, [20:55) c3 lex (i<=j<=k),
//            [55:60) ctc, [60:65) cts, [65] w0, [66] w1, [67] e0, [68] e1.

#define NBLK 1036            // 148 SMs * 7 CTAs
#define NTHR 128
#define TOTT (NBLK * NTHR)   // 132608 row-pairs per iteration

__constant__ float4 cC4[18]; // 72 floats; [69..71] zero padding

// Canonical-lex slot -> layer index (DFS order of _gen_exponents(5,3));
// verified bijection (R12/R13 passed with identical rel_err).
__device__ const int kPerm[65] = {
    0, 21, 36, 46, 52,
    1, 7, 12, 16, 19, 22, 27, 31, 34, 37, 41, 44, 47, 50, 53,
    2, 3, 4, 5, 6,
    8, 9, 10, 11,
    13, 14, 15,
    17, 18,
    20,
    23, 24, 25, 26,
    28, 29, 30,
    32, 33,
    35,
    38, 39, 40,
    42, 43,
    45,
    48, 49,
    51,
    54,
    55, 56, 57, 58, 59, 60, 61, 62, 63, 64
};

__global__ void ExternalForcesSI_setup_kernel(const float* __restrict__ layer,
                                              const float* __restrict__ omegas,
                                              const float* __restrict__ ef,
                                              float* __restrict__ cdst) {
    int tx = threadIdx.x;
    if (tx < 65)       cdst[tx] = layer[kPerm[tx]];
    else if (tx == 65) cdst[65] = omegas[0];
    else if (tx == 66) cdst[66] = omegas[1];
    else if (tx == 67) cdst[67] = ef[0];
    else if (tx == 68) cdst[68] = ef[1];
    else if (tx < 72)  cdst[tx] = 0.0f;     // pad: keep reads finite
}

struct Pair { float a[5]; float b[5]; };

__device__ __forceinline__ void load_pair(const float4* __restrict__ xp,
                                          const float2* __restrict__ tp,
                                          int off, Pair& P) {
    float4 x0 = xp[2 * off];
    float4 x1 = xp[2 * off + 1];
    float2 tt = tp[off];
    P.a[0] = x0.x; P.a[1] = x0.y; P.a[2] = x0.z; P.a[3] = x0.w; P.a[4] = tt.x;
    P.b[0] = x1.x; P.b[1] = x1.y; P.b[2] = x1.z; P.b[3] = x1.w; P.b[4] = tt.y;
}

// Materialize all 72 constants via 18 LDC.128s; indices static after unroll.
__device__ __forceinline__ void load_cc(float* cc) {
    #pragma unroll
    for (int m = 0; m < 18; m++) {
        float4 q = cC4[m];
        cc[4 * m + 0] = q.x;
        cc[4 * m + 1] = q.y;
        cc[4 * m + 2] = q.z;
        cc[4 * m + 3] = q.w;
    }
}

// Per-row polynomial + trig epilogue — EXACT R13 structure, cc[] source.
__device__ __forceinline__ float row_eval(const float* v,
                                          const float* C, const float* S,
                                          const float* cc) {
    float part[5];
    int q2 = 0, q3 = 0;
    #pragma unroll
    for (int i = 0; i < 5; i++) {
        float ui = cc[i];
        #pragma unroll
        for (int j = i; j < 5; j++) {
            float tij = cc[5 + q2]; q2++;
            #pragma unroll
            for (int k = j; k < 5; k++) {
                tij = fmaf(v[k], cc[20 + q3], tij); q3++;
            }
            ui = fmaf(v[j], tij, ui);
        }
        part[i] = v[i] * ui;
    }
    float a01 = fmaf(cc[55], C[0], cc[56] * C[1]);
    float a23 = fmaf(cc[57], C[2], cc[58] * C[3]);
    float b01 = fmaf(cc[60], S[0], cc[61] * S[1]);
    float b23 = fmaf(cc[62], S[2], cc[63] * S[3]);
    float a4  = fmaf(cc[59], C[4], cc[64] * S[4]);
    return (((part[0] + part[1]) + (part[2] + part[3])) + part[4])
           + (((a01 + a23) + (b01 + b23)) + a4);
}

template<int NITER>
__global__ __launch_bounds__(NTHR, 7)
void ExternalForcesSI_main_kernel(const float4* __restrict__ x,
                                  const float2* __restrict__ t2,
                                  float4* __restrict__ out,
                                  int npairs, int iters_rt) {
#if __CUDA_ARCH__ >= 900
    // PDL: setup grid's writes must be visible before reading cC4.
    cudaGridDependencySynchronize();
#endif
    const int tid = blockIdx.x * NTHR + threadIdx.x;
    const int pm1 = npairs - 1;
    const int iters = (NITER > 0) ? NITER : iters_rt;

    const float4* __restrict__ xp = x + 2 * tid;
    const float2* __restrict__ tp = t2 + tid;
    float4* __restrict__ op = out + tid;

    Pair buf[2];
    if (NITER > 0) load_pair(xp, tp, 0, buf[0]);
    else           load_pair(xp, tp, min(tid, pm1) - tid, buf[0]);

    #pragma unroll
    for (int it = 0; it < iters; it++) {
        const int cur = it & 1;
        const int nxt = cur ^ 1;

        // ---- prefetch next pair FIRST (LDGs fly during compute) ----
        if (it + 1 < iters) {
            if (NITER > 0 && it + 2 < iters) {
                load_pair(xp, tp, (it + 1) * TOTT, buf[nxt]);   // in-bounds
            } else {
                int pc = min(tid + (it + 1) * TOTT, pm1) - tid;
                load_pair(xp, tp, pc, buf[nxt]);
            }
        }

        // ---- constants: 18 LDC.128 per iteration (shared by both rows) ----
        float cc[72];
        load_cc(cc);
        const float w0 = cc[65];
        const float w1 = cc[66];
        const float e0 = cc[67];
        const float e1 = cc[68];

        const float* va = buf[cur].a;
        const float* vb = buf[cur].b;

        // ---- trig: issue all 20 MUFUs early (R13 tree form) ----
        float Ca[5], Sa[5], Cb[5], Sb[5];
        #pragma unroll
        for (int j = 0; j < 5; j++) {
            Ca[j] = __cosf(w0 * va[j]);
            Sa[j] = __sinf(w1 * va[j]);
            Cb[j] = __cosf(w0 * vb[j]);
            Sb[j] = __sinf(w1 * vb[j]);
        }

        float sA = row_eval(va, Ca, Sa, cc);
        float sB = row_eval(vb, Cb, Sb, cc);

        float4 res = make_float4(sA * e0, sA * e1, sB * e0, sB * e1);
        if (NITER > 0 && it + 1 < iters) {
            op[it * TOTT] = res;                      // provably in-bounds
        } else {
            if (tid + it * TOTT < npairs) op[it * TOTT] = res;
        }
    }
}

extern "C" void kernel_launch(void* const* d_in, const int* in_sizes, int n_in,
                              void* d_out, int out_size) {
    // metadata order: x, t, layer, omegas, ext_filter, E
    const float4* x      = (const float4*)d_in[0];
    const float2* t2     = (const float2*)d_in[1];
    const float*  layer  = (const float*)d_in[2];
    const float*  omegas = (const float*)d_in[3];
    const float*  ef     = (const float*)d_in[4];
    float4* out = (float4*)d_out;

    int n = in_sizes[1];              // N_DATA (element count of t), even
    int npairs = n >> 1;              // 500000
    int iters = (npairs + TOTT - 1) / TOTT;   // 4 for N=1M

    // Tiny setup node: permutation gather into the __constant__ backing store.
    static float* cdst = nullptr;     // host-side cache of the symbol address
    if (!cdst) cudaGetSymbolAddress((void**)&cdst, cC4);
    ExternalForcesSI_setup_kernel<<<1, 96>>>(layer, omegas, ef, cdst);

    // Main kernel with programmatic stream serialization (overlap launch ramp
    // with the setup node; ordering via cudaGridDependencySynchronize()).
    cudaLaunchConfig_t cfg = {};
    cfg.gridDim  = dim3(NBLK, 1, 1);
    cfg.blockDim = dim3(NTHR, 1, 1);
    cfg.dynamicSmemBytes = 0;
    cfg.stream = 0;
    cudaLaunchAttribute attrs[1];
    attrs[0].id = cudaLaunchAttributeProgrammaticStreamSerialization;
    attrs[0].val.programmaticStreamSerializationAllowed = 1;
    cfg.attrs = attrs;
    cfg.numAttrs = 1;

    if (iters == 4 && (iters - 1) * TOTT <= npairs) {
        cudaLaunchKernelEx(&cfg, ExternalForcesSI_main_kernel<4>,
                           x, t2, out, npairs, iters);
    } else {
        cudaLaunchKernelEx(&cfg, ExternalForcesSI_main_kernel<0>,
                           x, t2, out, npairs, iters);
    }
}